// round 3
// baseline (speedup 1.0000x reference)
#include <cuda_runtime.h>
#include <cstdint>

// Problem constants (fixed shapes for this instance)
#define N_NODES 50000
#define N_EDGES 600000
#define CH      128          // IN_CH == OUT_CH == 128, HEADS == 1
#define CAP     96           // per-node bucket capacity (Poisson(12): overflow ~impossible)
#define OVF_MAX 16384        // overflow edge list capacity (correctness fallback)

// ---------------------------------------------------------------------------
// Scratch (no cudaMalloc allowed)
// ---------------------------------------------------------------------------
__device__ int d_deg[N_NODES];                   // in-degree (excl. self loop)
__device__ int d_bucket[(size_t)N_NODES * CAP];  // per-dst source lists
__device__ int d_is64;                           // edge_index dtype flag
__device__ int d_ovf_cnt;                        // overflow edge count
__device__ int d_ovf[OVF_MAX * 2];               // overflow (src,dst) pairs

// ---------------------------------------------------------------------------
// Zero: deg = 0, ovf_cnt = 0, and sniff edge dtype (thread 0 of block 0).
// int64 indices < 50000 -> high word always 0; int32 read as u64 -> nonzero.
// ---------------------------------------------------------------------------
__global__ void zero_kernel(const void* __restrict__ ei, int n_nodes) {
    int i = blockIdx.x * blockDim.x + threadIdx.x;
    if (i < n_nodes) d_deg[i] = 0;
    if (i == 0) {
        d_ovf_cnt = 0;
        const unsigned long long* p = (const unsigned long long*)ei;
        int is64 = 1;
        #pragma unroll
        for (int j = 0; j < 16; j++)
            if (p[j] >> 32) is64 = 0;
        d_is64 = is64;
    }
}

// ---------------------------------------------------------------------------
// Histogram + bucket fill: thread per edge.
// Overflow (never expected for this input) appends to a small list.
// ---------------------------------------------------------------------------
__global__ void histo_fill_kernel(const void* __restrict__ ei, int n_edges) {
    int e = blockIdx.x * blockDim.x + threadIdx.x;
    if (e >= n_edges) return;

    int src, dst;
    if (d_is64) {
        const long long* p = (const long long*)ei;
        src = (int)p[e];
        dst = (int)p[n_edges + e];
    } else {
        const int* p = (const int*)ei;
        src = p[e];
        dst = p[n_edges + e];
    }

    int pos = atomicAdd(&d_deg[dst], 1);
    if (pos < CAP) {
        d_bucket[dst * CAP + pos] = src;
    } else {
        int j = atomicAdd(&d_ovf_cnt, 1);
        if (j < OVF_MAX) {
            d_ovf[2 * j]     = src;
            d_ovf[2 * j + 1] = dst;
        }
    }
}

// ---------------------------------------------------------------------------
// Fused gather + GEMM + epilogue.
// Phase 1: block gathers its 128 rows (self + neighbors) into smem A tile.
//          Warp per row, lane owns one float4 of the 128-wide row.
// Phase 2: out = relu( (A @ W) / (deg+1) + bias ), BN=128, BK=16,
//          256 threads, 8x8 microtile split 2x(4) x 2x(4).
// A stored row-major [m][132] (conflict-free vec stores; GEMM a-reads are
// scalar, only 2 distinct rows per warp -> broadcast).
// ---------------------------------------------------------------------------
#define A_LD 132   // padded row length

__global__ __launch_bounds__(256, 2)
void fused_kernel(const float* __restrict__ x,
                  const float* __restrict__ W,
                  const float* __restrict__ bias,
                  float* __restrict__ out,
                  int n_nodes) {
    extern __shared__ float smem[];
    float* As = smem;                 // [128][A_LD]
    float* Bs = smem + 128 * A_LD;    // [16][128]

    int tid  = threadIdx.x;
    int warp = tid >> 5;
    int lane = tid & 31;
    int row0 = blockIdx.x * 128;

    // ---------------- Phase 1: gather ----------------
    for (int it = 0; it < 16; it++) {
        int m = warp * 16 + it;
        int r = row0 + m;
        float4 acc = make_float4(0.f, 0.f, 0.f, 0.f);
        if (r < n_nodes) {
            acc = *(const float4*)(x + (size_t)r * CH + lane * 4);   // self loop
            int deg = d_deg[r];
            int nb  = min(deg, CAP);
            int base = r * CAP;
            for (int e0 = 0; e0 < nb; e0 += 32) {
                int idx = 0;
                if (e0 + lane < nb) idx = d_bucket[base + e0 + lane];
                int mm = min(32, nb - e0);
                int t = 0;
                for (; t + 4 <= mm; t += 4) {
                    int s0 = __shfl_sync(0xFFFFFFFFu, idx, t);
                    int s1 = __shfl_sync(0xFFFFFFFFu, idx, t + 1);
                    int s2 = __shfl_sync(0xFFFFFFFFu, idx, t + 2);
                    int s3 = __shfl_sync(0xFFFFFFFFu, idx, t + 3);
                    float4 v0 = *(const float4*)(x + (size_t)s0 * CH + lane * 4);
                    float4 v1 = *(const float4*)(x + (size_t)s1 * CH + lane * 4);
                    float4 v2 = *(const float4*)(x + (size_t)s2 * CH + lane * 4);
                    float4 v3 = *(const float4*)(x + (size_t)s3 * CH + lane * 4);
                    acc.x += v0.x + v1.x + v2.x + v3.x;
                    acc.y += v0.y + v1.y + v2.y + v3.y;
                    acc.z += v0.z + v1.z + v2.z + v3.z;
                    acc.w += v0.w + v1.w + v2.w + v3.w;
                }
                for (; t < mm; t++) {
                    int s = __shfl_sync(0xFFFFFFFFu, idx, t);
                    float4 v = *(const float4*)(x + (size_t)s * CH + lane * 4);
                    acc.x += v.x; acc.y += v.y; acc.z += v.z; acc.w += v.w;
                }
            }
            if (deg > CAP) {   // correctness fallback, never taken on this input
                int oc = min(d_ovf_cnt, OVF_MAX);
                for (int o = 0; o < oc; o++) {
                    if (d_ovf[2 * o + 1] == r) {
                        int s = d_ovf[2 * o];
                        float4 v = *(const float4*)(x + (size_t)s * CH + lane * 4);
                        acc.x += v.x; acc.y += v.y; acc.z += v.z; acc.w += v.w;
                    }
                }
            }
        }
        *(float4*)(As + m * A_LD + lane * 4) = acc;
    }
    __syncthreads();

    // ---------------- Phase 2: GEMM ----------------
    int tx = tid & 15;     // col group
    int ty = tid >> 4;     // row group

    float acc[2][4][2][4];
    #pragma unroll
    for (int ri = 0; ri < 2; ri++)
        #pragma unroll
        for (int i = 0; i < 4; i++)
            #pragma unroll
            for (int ci = 0; ci < 2; ci++)
                #pragma unroll
                for (int j = 0; j < 4; j++)
                    acc[ri][i][ci][j] = 0.0f;

    for (int k0 = 0; k0 < CH; k0 += 16) {
        // Stream B tile: Bs[k][n] = W[(k0+k)*CH + n]
        #pragma unroll
        for (int i = 0; i < 2; i++) {
            int f  = tid + i * 256;     // 0..511
            int k  = f >> 5;
            int n4 = f & 31;
            *(float4*)&Bs[k * 128 + n4 * 4] =
                *(const float4*)(W + (size_t)(k0 + k) * CH + n4 * 4);
        }
        __syncthreads();

        #pragma unroll
        for (int kk = 0; kk < 16; kk++) {
            float a[2][4];
            #pragma unroll
            for (int ri = 0; ri < 2; ri++)
                #pragma unroll
                for (int i = 0; i < 4; i++)
                    a[ri][i] = As[(ri * 64 + ty * 4 + i) * A_LD + k0 + kk];
            float4 b0 = *(const float4*)&Bs[kk * 128 + tx * 4];
            float4 b1 = *(const float4*)&Bs[kk * 128 + 64 + tx * 4];
            float b[2][4] = {{b0.x, b0.y, b0.z, b0.w}, {b1.x, b1.y, b1.z, b1.w}};
            #pragma unroll
            for (int ri = 0; ri < 2; ri++)
                #pragma unroll
                for (int i = 0; i < 4; i++)
                    #pragma unroll
                    for (int ci = 0; ci < 2; ci++)
                        #pragma unroll
                        for (int j = 0; j < 4; j++)
                            acc[ri][i][ci][j] = fmaf(a[ri][i], b[ci][j], acc[ri][i][ci][j]);
        }
        __syncthreads();
    }

    // ---------------- Epilogue: /(deg+1), +bias, relu ----------------
    float4 bb0 = *(const float4*)(bias + tx * 4);
    float4 bb1 = *(const float4*)(bias + 64 + tx * 4);
    float bb[2][4] = {{bb0.x, bb0.y, bb0.z, bb0.w}, {bb1.x, bb1.y, bb1.z, bb1.w}};

    #pragma unroll
    for (int ri = 0; ri < 2; ri++) {
        #pragma unroll
        for (int i = 0; i < 4; i++) {
            int r = row0 + ri * 64 + ty * 4 + i;
            if (r < n_nodes) {
                float inv = 1.0f / (float)(d_deg[r] + 1);
                #pragma unroll
                for (int ci = 0; ci < 2; ci++) {
                    float4 o;
                    o.x = fmaxf(fmaf(acc[ri][i][ci][0], inv, bb[ci][0]), 0.0f);
                    o.y = fmaxf(fmaf(acc[ri][i][ci][1], inv, bb[ci][1]), 0.0f);
                    o.z = fmaxf(fmaf(acc[ri][i][ci][2], inv, bb[ci][2]), 0.0f);
                    o.w = fmaxf(fmaf(acc[ri][i][ci][3], inv, bb[ci][3]), 0.0f);
                    *(float4*)(out + (size_t)r * CH + ci * 64 + tx * 4) = o;
                }
            }
        }
    }
}

// ---------------------------------------------------------------------------
// kernel_launch
// Inputs: x[f32 N*128], edge_index[2*E], weight[f32 128*128],
//         u[f32 128], c[f32 1], bias[f32 128]
// u, c are dead: HEADS==1 => softmax over one element == 1.
// ---------------------------------------------------------------------------
extern "C" void kernel_launch(void* const* d_in, const int* in_sizes, int n_in,
                              void* d_out, int out_size) {
    const float* x    = (const float*)d_in[0];
    const void*  ei   = d_in[1];
    const float* W    = (const float*)d_in[2];
    const float* bias = (const float*)d_in[5];
    float* out = (float*)d_out;

    int n_nodes = in_sizes[0] / CH;
    int n_edges = in_sizes[1] / 2;

    const int smem_bytes = (128 * A_LD + 16 * 128) * sizeof(float);  // 75776 B
    static bool attr_set = false;
    if (!attr_set) {
        cudaFuncSetAttribute(fused_kernel,
                             cudaFuncAttributeMaxDynamicSharedMemorySize,
                             smem_bytes);
        attr_set = true;
    }

    zero_kernel<<<(n_nodes + 255) / 256, 256>>>(ei, n_nodes);
    histo_fill_kernel<<<(n_edges + 255) / 256, 256>>>(ei, n_edges);
    fused_kernel<<<(n_nodes + 127) / 128, 256, smem_bytes>>>(x, W, bias, out, n_nodes);
}

// round 4
// speedup vs baseline: 1.0061x; 1.0061x over previous
#include <cuda_runtime.h>
#include <cstdint>

// Problem constants (fixed shapes for this instance)
#define N_NODES 50000
#define N_EDGES 600000
#define CH      128          // IN_CH == OUT_CH == 128, HEADS == 1
#define CAP     96           // per-node bucket capacity (Poisson(12): overflow ~impossible)
#define OVF_MAX 16384        // overflow edge list capacity (correctness fallback)

// ---------------------------------------------------------------------------
// Scratch (no cudaMalloc allowed)
// ---------------------------------------------------------------------------
__device__ float d_s[(size_t)N_NODES * CH];        // aggregated features
__device__ int   d_deg[N_NODES];                   // in-degree (excl. self loop)
__device__ int   d_bucket[(size_t)N_NODES * CAP];  // per-dst source lists
__device__ int   d_is64;                           // edge_index dtype flag
__device__ int   d_ovf_cnt;                        // overflow edge count
__device__ int   d_ovf[OVF_MAX * 2];               // overflow (src,dst) pairs

// ---------------------------------------------------------------------------
// Zero: deg = 0, ovf_cnt = 0, sniff edge dtype. (d_s needs no zeroing: the
// gather kernel writes every row it owns exactly once.)
// ---------------------------------------------------------------------------
__global__ void zero_kernel(const void* __restrict__ ei, int n_nodes) {
    int i = blockIdx.x * blockDim.x + threadIdx.x;
    if (i < n_nodes) d_deg[i] = 0;
    if (i == 0) {
        d_ovf_cnt = 0;
        const unsigned long long* p = (const unsigned long long*)ei;
        int is64 = 1;
        #pragma unroll
        for (int j = 0; j < 16; j++)
            if (p[j] >> 32) is64 = 0;
        d_is64 = is64;
    }
}

// ---------------------------------------------------------------------------
// Histogram + bucket fill: thread per edge. Overflow -> small (src,dst) list.
// ---------------------------------------------------------------------------
__global__ void histo_fill_kernel(const void* __restrict__ ei, int n_edges) {
    int e = blockIdx.x * blockDim.x + threadIdx.x;
    if (e >= n_edges) return;

    int src, dst;
    if (d_is64) {
        const long long* p = (const long long*)ei;
        src = (int)p[e];
        dst = (int)p[n_edges + e];
    } else {
        const int* p = (const int*)ei;
        src = p[e];
        dst = p[n_edges + e];
    }

    int pos = atomicAdd(&d_deg[dst], 1);
    if (pos < CAP) {
        d_bucket[dst * CAP + pos] = src;
    } else {
        int j = atomicAdd(&d_ovf_cnt, 1);
        if (j < OVF_MAX) {
            d_ovf[2 * j]     = src;
            d_ovf[2 * j + 1] = dst;
        }
    }
}

// ---------------------------------------------------------------------------
// Gather: warp per node. acc = x[node] + sum of bucketed neighbor rows
// (+ overflow list matches, never taken here). One d_s row write per node.
// ---------------------------------------------------------------------------
__global__ void gather_kernel(const float* __restrict__ x, int n_nodes) {
    int node = (blockIdx.x * blockDim.x + threadIdx.x) >> 5;
    int lane = threadIdx.x & 31;
    if (node >= n_nodes) return;

    int deg = d_deg[node];
    int nb  = min(deg, CAP);

    const size_t rb = (size_t)node * CH + lane * 4;
    float4 acc = *(const float4*)(x + rb);          // self loop

    int base = node * CAP;
    for (int e0 = 0; e0 < nb; e0 += 32) {
        int idx = 0;
        if (e0 + lane < nb) idx = d_bucket[base + e0 + lane];
        int m = min(32, nb - e0);
        int t = 0;
        for (; t + 4 <= m; t += 4) {
            int s0 = __shfl_sync(0xFFFFFFFFu, idx, t);
            int s1 = __shfl_sync(0xFFFFFFFFu, idx, t + 1);
            int s2 = __shfl_sync(0xFFFFFFFFu, idx, t + 2);
            int s3 = __shfl_sync(0xFFFFFFFFu, idx, t + 3);
            float4 v0 = *(const float4*)(x + (size_t)s0 * CH + lane * 4);
            float4 v1 = *(const float4*)(x + (size_t)s1 * CH + lane * 4);
            float4 v2 = *(const float4*)(x + (size_t)s2 * CH + lane * 4);
            float4 v3 = *(const float4*)(x + (size_t)s3 * CH + lane * 4);
            acc.x += v0.x + v1.x + v2.x + v3.x;
            acc.y += v0.y + v1.y + v2.y + v3.y;
            acc.z += v0.z + v1.z + v2.z + v3.z;
            acc.w += v0.w + v1.w + v2.w + v3.w;
        }
        for (; t < m; t++) {
            int s = __shfl_sync(0xFFFFFFFFu, idx, t);
            float4 v = *(const float4*)(x + (size_t)s * CH + lane * 4);
            acc.x += v.x; acc.y += v.y; acc.z += v.z; acc.w += v.w;
        }
    }
    if (deg > CAP) {   // correctness fallback, never taken on this input
        int oc = min(d_ovf_cnt, OVF_MAX);
        for (int o = 0; o < oc; o++) {
            if (d_ovf[2 * o + 1] == node) {
                int s = d_ovf[2 * o];
                float4 v = *(const float4*)(x + (size_t)s * CH + lane * 4);
                acc.x += v.x; acc.y += v.y; acc.z += v.z; acc.w += v.w;
            }
        }
    }
    *(float4*)(d_s + rb) = acc;
}

// ---------------------------------------------------------------------------
// GEMM + epilogue with packed fp32 FMA (fma.rn.f32x2):
//   out = relu( (s @ W) / (deg+1) + bias )
// BM=BN=128, BK=16, 256 threads, 8x8 microtile.
// A pairs = two adjacent M-rows per 64-bit lane; B duplicated in smem so each
// 64-bit lane is (b, b). Per kk-step: 6 x LDS.128 + 32 x FMA2 (=64 FLOPs).
// ---------------------------------------------------------------------------
#define FMA2(acc, a, b) \
    asm("fma.rn.f32x2 %0, %1, %2, %3;" : "=l"(acc) : "l"(a), "l"(b), "l"(acc))

__device__ __forceinline__ void unpack2(unsigned long long v, float& lo, float& hi) {
    asm("mov.b64 {%0, %1}, %2;" : "=f"(lo), "=f"(hi) : "l"(v));
}

__global__ __launch_bounds__(256, 2)
void gemm_kernel(const float* __restrict__ W,
                 const float* __restrict__ bias,
                 float* __restrict__ out,
                 int n_nodes) {
    __shared__ float As[16][132];    // [k][m] transposed, pad keeps 16B align
    __shared__ float Bd[16][256];    // [k][2n] duplicated: Bd[k][2n]=Bd[k][2n+1]=W[k][n]

    int tid = threadIdx.x;
    int tx  = tid & 15;    // col group: cols tx*4..+3 and 64+tx*4..+3
    int ty  = tid >> 4;    // row group: rows ty*4..+3 and 64+ty*4..+3
    int row0 = blockIdx.x * 128;

    // acc[rp][j]: rp = row-pair (0: ty*4+{0,1}, 1: ty*4+{2,3}, 2/3: +64),
    //             j  = col (0..3: tx*4+j, 4..7: 64+tx*4+j-4)
    unsigned long long acc[4][8];
    #pragma unroll
    for (int rp = 0; rp < 4; rp++)
        #pragma unroll
        for (int j = 0; j < 8; j++) acc[rp][j] = 0ULL;

    for (int k0 = 0; k0 < CH; k0 += 16) {
        // A tile: As[k][m] = s[(row0+m)*CH + k0+k], float4 along k, transpose
        #pragma unroll
        for (int i = 0; i < 2; i++) {
            int f  = tid + i * 256;      // 0..511
            int m  = f >> 2;
            int kq = f & 3;
            int rg = row0 + m;
            float4 v = make_float4(0.f, 0.f, 0.f, 0.f);
            if (rg < n_nodes)
                v = *(const float4*)(d_s + (size_t)rg * CH + k0 + kq * 4);
            As[kq * 4 + 0][m] = v.x;
            As[kq * 4 + 1][m] = v.y;
            As[kq * 4 + 2][m] = v.z;
            As[kq * 4 + 3][m] = v.w;
        }
        // B tile duplicated: 16 k x 64 col-pairs, 4 iters of 256 threads
        #pragma unroll
        for (int i = 0; i < 4; i++) {
            int f  = tid + i * 256;      // 0..1023
            int k  = f >> 6;
            int np = f & 63;
            float2 w = *(const float2*)(W + (size_t)(k0 + k) * CH + np * 2);
            *(float4*)&Bd[k][np * 4] = make_float4(w.x, w.x, w.y, w.y);
        }
        __syncthreads();

        #pragma unroll
        for (int kk = 0; kk < 16; kk++) {
            ulonglong2 a0 = *(const ulonglong2*)&As[kk][ty * 4];        // rows ty*4+{0,1},{2,3}
            ulonglong2 a1 = *(const ulonglong2*)&As[kk][64 + ty * 4];
            ulonglong2 b0 = *(const ulonglong2*)&Bd[kk][tx * 8];        // cols tx*4+0,1 (dup)
            ulonglong2 b1 = *(const ulonglong2*)&Bd[kk][tx * 8 + 4];    // cols tx*4+2,3
            ulonglong2 b2 = *(const ulonglong2*)&Bd[kk][128 + tx * 8];  // cols 64+tx*4+0,1
            ulonglong2 b3 = *(const ulonglong2*)&Bd[kk][128 + tx * 8 + 4];
            unsigned long long ap[4] = {a0.x, a0.y, a1.x, a1.y};
            unsigned long long bp[8] = {b0.x, b0.y, b1.x, b1.y, b2.x, b2.y, b3.x, b3.y};
            #pragma unroll
            for (int rp = 0; rp < 4; rp++)
                #pragma unroll
                for (int j = 0; j < 8; j++)
                    FMA2(acc[rp][j], ap[rp], bp[j]);
        }
        __syncthreads();
    }

    // Epilogue: /(deg+1), +bias, relu
    float bb[8];
    {
        float4 bb0 = *(const float4*)(bias + tx * 4);
        float4 bb1 = *(const float4*)(bias + 64 + tx * 4);
        bb[0] = bb0.x; bb[1] = bb0.y; bb[2] = bb0.z; bb[3] = bb0.w;
        bb[4] = bb1.x; bb[5] = bb1.y; bb[6] = bb1.z; bb[7] = bb1.w;
    }

    #pragma unroll
    for (int half = 0; half < 2; half++) {
        #pragma unroll
        for (int pr = 0; pr < 2; pr++) {
            int rp = half * 2 + pr;
            #pragma unroll
            for (int sub = 0; sub < 2; sub++) {
                int r = row0 + half * 64 + ty * 4 + pr * 2 + sub;
                if (r < n_nodes) {
                    float inv = 1.0f / (float)(d_deg[r] + 1);
                    float o[8];
                    #pragma unroll
                    for (int j = 0; j < 8; j++) {
                        float lo, hi;
                        unpack2(acc[rp][j], lo, hi);
                        float v = sub ? hi : lo;
                        o[j] = fmaxf(fmaf(v, inv, bb[j]), 0.0f);
                    }
                    *(float4*)(out + (size_t)r * CH + tx * 4) =
                        make_float4(o[0], o[1], o[2], o[3]);
                    *(float4*)(out + (size_t)r * CH + 64 + tx * 4) =
                        make_float4(o[4], o[5], o[6], o[7]);
                }
            }
        }
    }
}

// ---------------------------------------------------------------------------
// kernel_launch
// Inputs: x[f32 N*128], edge_index[2*E], weight[f32 128*128],
//         u[f32 128], c[f32 1], bias[f32 128]
// u, c are dead: HEADS==1 => softmax over one element == 1.
// ---------------------------------------------------------------------------
extern "C" void kernel_launch(void* const* d_in, const int* in_sizes, int n_in,
                              void* d_out, int out_size) {
    const float* x    = (const float*)d_in[0];
    const void*  ei   = d_in[1];
    const float* W    = (const float*)d_in[2];
    const float* bias = (const float*)d_in[5];
    float* out = (float*)d_out;

    int n_nodes = in_sizes[0] / CH;
    int n_edges = in_sizes[1] / 2;

    zero_kernel<<<(n_nodes + 255) / 256, 256>>>(ei, n_nodes);
    histo_fill_kernel<<<(n_edges + 255) / 256, 256>>>(ei, n_edges);
    gather_kernel<<<(n_nodes * 32 + 255) / 256, 256>>>(x, n_nodes);
    gemm_kernel<<<(n_nodes + 127) / 128, 256>>>(W, bias, out, n_nodes);
}

// round 6
// speedup vs baseline: 1.4171x; 1.4085x over previous
#include <cuda_runtime.h>
#include <cuda_bf16.h>
#include <cstdint>

// Problem constants (fixed shapes for this instance)
#define N_NODES 50000
#define N_EDGES 600000
#define CH      128          // IN_CH == OUT_CH == 128, HEADS == 1
#define CAP     96           // per-node bucket capacity
#define OVF_MAX 16384        // overflow edge list capacity (correctness fallback)

#define LDA 136              // padded bf16 row stride (272 B) for ldmatrix tiles

// ---------------------------------------------------------------------------
// Scratch (no cudaMalloc allowed)
// ---------------------------------------------------------------------------
__device__ float d_s[(size_t)N_NODES * CH];        // aggregated features
__device__ int   d_deg[N_NODES];                   // in-degree (excl. self loop)
__device__ int   d_bucket[(size_t)N_NODES * CAP];  // per-dst source lists
__device__ int   d_is64;                           // edge_index dtype flag
__device__ int   d_ovf_cnt;
__device__ int   d_ovf[OVF_MAX * 2];
// W pre-transposed to [n][k] (k contiguous), bf16 hi/lo split, padded to LDA.
__device__ __nv_bfloat16 d_Whi[CH * LDA];
__device__ __nv_bfloat16 d_Wlo[CH * LDA];

// ---------------------------------------------------------------------------
// MMA helpers (baseline PTX, legal on plain sm_103)
// ---------------------------------------------------------------------------
__device__ __forceinline__ uint32_t smem_to_u32(const void* p) {
    uint32_t a;
    asm("{ .reg .u64 t; cvta.to.shared.u64 t, %1; cvt.u32.u64 %0, t; }"
        : "=r"(a) : "l"(p));
    return a;
}
__device__ __forceinline__ void ldsm_x4(uint32_t* r, uint32_t addr) {
    asm volatile("ldmatrix.sync.aligned.m8n8.x4.shared.b16 {%0,%1,%2,%3}, [%4];"
                 : "=r"(r[0]), "=r"(r[1]), "=r"(r[2]), "=r"(r[3]) : "r"(addr));
}
__device__ __forceinline__ void mma_bf16(float* c, const uint32_t* a,
                                         uint32_t b0, uint32_t b1) {
    asm volatile("mma.sync.aligned.m16n8k16.row.col.f32.bf16.bf16.f32 "
                 "{%0,%1,%2,%3}, {%4,%5,%6,%7}, {%8,%9}, {%0,%1,%2,%3};"
                 : "+f"(c[0]), "+f"(c[1]), "+f"(c[2]), "+f"(c[3])
                 : "r"(a[0]), "r"(a[1]), "r"(a[2]), "r"(a[3]), "r"(b0), "r"(b1));
}

// ---------------------------------------------------------------------------
// Zero + dtype sniff
// ---------------------------------------------------------------------------
__global__ void zero_kernel(const void* __restrict__ ei, int n_nodes) {
    int i = blockIdx.x * blockDim.x + threadIdx.x;
    if (i < n_nodes) d_deg[i] = 0;
    if (i == 0) {
        d_ovf_cnt = 0;
        const unsigned long long* p = (const unsigned long long*)ei;
        int is64 = 1;
        #pragma unroll
        for (int j = 0; j < 16; j++)
            if (p[j] >> 32) is64 = 0;
        d_is64 = is64;
    }
}

// ---------------------------------------------------------------------------
// W prep: transpose to [n][k] (k contiguous), bf16 hi/lo split, pad k to LDA.
// ---------------------------------------------------------------------------
__global__ void wprep_kernel(const float* __restrict__ W) {
    int idx = blockIdx.x * blockDim.x + threadIdx.x;
    if (idx >= CH * LDA) return;
    int n = idx / LDA;
    int k = idx % LDA;
    float w = (k < CH) ? W[(size_t)k * CH + n] : 0.0f;
    __nv_bfloat16 hi = __float2bfloat16(w);
    __nv_bfloat16 lo = __float2bfloat16(w - __bfloat162float(hi));
    d_Whi[idx] = hi;
    d_Wlo[idx] = lo;
}

// ---------------------------------------------------------------------------
// Histogram + bucket fill
// ---------------------------------------------------------------------------
__global__ void histo_fill_kernel(const void* __restrict__ ei, int n_edges) {
    int e = blockIdx.x * blockDim.x + threadIdx.x;
    if (e >= n_edges) return;
    int src, dst;
    if (d_is64) {
        const long long* p = (const long long*)ei;
        src = (int)p[e];
        dst = (int)p[n_edges + e];
    } else {
        const int* p = (const int*)ei;
        src = p[e];
        dst = p[n_edges + e];
    }
    int pos = atomicAdd(&d_deg[dst], 1);
    if (pos < CAP) {
        d_bucket[dst * CAP + pos] = src;
    } else {
        int j = atomicAdd(&d_ovf_cnt, 1);
        if (j < OVF_MAX) { d_ovf[2 * j] = src; d_ovf[2 * j + 1] = dst; }
    }
}

// ---------------------------------------------------------------------------
// Gather: warp per node (measured at the LTS cap)
// ---------------------------------------------------------------------------
__global__ void gather_kernel(const float* __restrict__ x, int n_nodes) {
    int node = (blockIdx.x * blockDim.x + threadIdx.x) >> 5;
    int lane = threadIdx.x & 31;
    if (node >= n_nodes) return;

    int deg = d_deg[node];
    int nb  = min(deg, CAP);
    const size_t rb = (size_t)node * CH + lane * 4;
    float4 acc = *(const float4*)(x + rb);          // self loop

    int base = node * CAP;
    for (int e0 = 0; e0 < nb; e0 += 32) {
        int idx = 0;
        if (e0 + lane < nb) idx = d_bucket[base + e0 + lane];
        int m = min(32, nb - e0);
        int t = 0;
        for (; t + 4 <= m; t += 4) {
            int s0 = __shfl_sync(0xFFFFFFFFu, idx, t);
            int s1 = __shfl_sync(0xFFFFFFFFu, idx, t + 1);
            int s2 = __shfl_sync(0xFFFFFFFFu, idx, t + 2);
            int s3 = __shfl_sync(0xFFFFFFFFu, idx, t + 3);
            float4 v0 = *(const float4*)(x + (size_t)s0 * CH + lane * 4);
            float4 v1 = *(const float4*)(x + (size_t)s1 * CH + lane * 4);
            float4 v2 = *(const float4*)(x + (size_t)s2 * CH + lane * 4);
            float4 v3 = *(const float4*)(x + (size_t)s3 * CH + lane * 4);
            acc.x += v0.x + v1.x + v2.x + v3.x;
            acc.y += v0.y + v1.y + v2.y + v3.y;
            acc.z += v0.z + v1.z + v2.z + v3.z;
            acc.w += v0.w + v1.w + v2.w + v3.w;
        }
        for (; t < m; t++) {
            int s = __shfl_sync(0xFFFFFFFFu, idx, t);
            float4 v = *(const float4*)(x + (size_t)s * CH + lane * 4);
            acc.x += v.x; acc.y += v.y; acc.z += v.z; acc.w += v.w;
        }
    }
    if (deg > CAP) {   // never taken on this input
        int oc = min(d_ovf_cnt, OVF_MAX);
        for (int o = 0; o < oc; o++) {
            if (d_ovf[2 * o + 1] == node) {
                int s = d_ovf[2 * o];
                float4 v = *(const float4*)(x + (size_t)s * CH + lane * 4);
                acc.x += v.x; acc.y += v.y; acc.z += v.z; acc.w += v.w;
            }
        }
    }
    *(float4*)(d_s + rb) = acc;
}

// ---------------------------------------------------------------------------
// Warp-MMA GEMM (bf16 HMMA, 3-term split): out = relu((s@W)/(deg+1) + bias)
// CTA: 128 rows x 128 cols x K=128. 8 warps, warp tile 32x64.
// A_hi/A_lo: [m][k] bf16 (stride LDA), B_hi/B_lo: [n][k] bf16 (stride LDA).
// ---------------------------------------------------------------------------
#define SA_HI 0
#define SA_LO (128 * LDA * 2)            // 34816
#define SB_HI (2 * 128 * LDA * 2)        // 69632
#define SB_LO (3 * 128 * LDA * 2)        // 104448
#define SM_TOTAL (4 * 128 * LDA * 2)     // 139264

__global__ __launch_bounds__(256, 1)
void gemm_mma_kernel(const float* __restrict__ bias,
                     float* __restrict__ out,
                     int n_nodes) {
    extern __shared__ char smem[];
    uint32_t sb = smem_to_u32(smem);
    int tid  = threadIdx.x;
    int wid  = tid >> 5;
    int lane = tid & 31;
    int row0 = blockIdx.x * 128;

    // ---- Load + convert A tile (hi/lo bf16), 2 threads per row ----
    {
        int row  = tid >> 1;
        int half = (tid & 1) * 64;
        int rg   = row0 + row;
        const float* p = d_s + (size_t)rg * CH + half;
        #pragma unroll
        for (int j = 0; j < 64; j += 8) {
            float f[8];
            if (rg < n_nodes) {
                float4 va = *(const float4*)(p + j);
                float4 vb = *(const float4*)(p + j + 4);
                f[0]=va.x; f[1]=va.y; f[2]=va.z; f[3]=va.w;
                f[4]=vb.x; f[5]=vb.y; f[6]=vb.z; f[7]=vb.w;
            } else {
                #pragma unroll
                for (int i = 0; i < 8; i++) f[i] = 0.0f;
            }
            union { __nv_bfloat16 b[8]; uint4 v; } hi, lo;
            #pragma unroll
            for (int i = 0; i < 8; i++) {
                hi.b[i] = __float2bfloat16(f[i]);
                lo.b[i] = __float2bfloat16(f[i] - __bfloat162float(hi.b[i]));
            }
            size_t off = ((size_t)row * LDA + half + j) * 2;
            *(uint4*)(smem + SA_HI + off) = hi.v;
            *(uint4*)(smem + SA_LO + off) = lo.v;
        }
    }
    // ---- Copy pre-split B tiles (linear, 2176 uint4 each) ----
    {
        const uint4* shi = (const uint4*)d_Whi;
        const uint4* slo = (const uint4*)d_Wlo;
        uint4* dhi = (uint4*)(smem + SB_HI);
        uint4* dlo = (uint4*)(smem + SB_LO);
        #pragma unroll
        for (int i = 0; i < 9; i++) {
            int idx = tid + i * 256;
            if (idx < (128 * LDA * 2) / 16) {
                dhi[idx] = shi[idx];
                dlo[idx] = slo[idx];
            }
        }
    }
    __syncthreads();

    // ---- Warp MMA mainloop ----
    int mw = (wid >> 1) * 32;      // warp M offset
    int nw = (wid & 1) * 64;       // warp N offset
    int lr = lane & 15;
    int lh = lane >> 4;

    float acc[2][8][4];
    #pragma unroll
    for (int mi = 0; mi < 2; mi++)
        #pragma unroll
        for (int t = 0; t < 8; t++)
            #pragma unroll
            for (int j = 0; j < 4; j++) acc[mi][t][j] = 0.0f;

    #pragma unroll
    for (int kk = 0; kk < 8; kk++) {
        int k0 = kk * 16;
        uint32_t ahi[2][4], alo[2][4], bhi[4][4], blo[4][4];
        #pragma unroll
        for (int mi = 0; mi < 2; mi++) {
            uint32_t ar = sb + SA_HI + ((mw + mi * 16 + lr) * LDA + k0 + lh * 8) * 2;
            ldsm_x4(ahi[mi], ar);
            ldsm_x4(alo[mi], ar + (SA_LO - SA_HI));
        }
        #pragma unroll
        for (int nj = 0; nj < 4; nj++) {
            uint32_t br = sb + SB_HI + ((nw + nj * 16 + lr) * LDA + k0 + lh * 8) * 2;
            ldsm_x4(bhi[nj], br);
            ldsm_x4(blo[nj], br + (SB_LO - SB_HI));
        }
        #pragma unroll
        for (int mi = 0; mi < 2; mi++) {
            #pragma unroll
            for (int t = 0; t < 8; t++) {
                int nj  = t >> 1;
                int sel = t & 1;
                uint32_t bh0 = bhi[nj][sel],     bh1 = bhi[nj][sel + 2];
                uint32_t bl0 = blo[nj][sel],     bl1 = blo[nj][sel + 2];
                mma_bf16(acc[mi][t], ahi[mi], bh0, bh1);   // hi*hi
                mma_bf16(acc[mi][t], ahi[mi], bl0, bl1);   // hi*lo
                mma_bf16(acc[mi][t], alo[mi], bh0, bh1);   // lo*hi
            }
        }
    }

    // ---- Epilogue: /(deg+1), +bias, relu ----
    int qr = lane >> 2;
    int qc = lane & 3;
    #pragma unroll
    for (int mi = 0; mi < 2; mi++) {
        int ra = row0 + mw + mi * 16 + qr;
        int rb2 = ra + 8;
        bool va = ra < n_nodes, vb = rb2 < n_nodes;
        float inva = va ? 1.0f / (float)(d_deg[ra] + 1) : 0.0f;
        float invb = vb ? 1.0f / (float)(d_deg[rb2] + 1) : 0.0f;
        #pragma unroll
        for (int t = 0; t < 8; t++) {
            int col = nw + t * 8 + qc * 2;
            float2 bb = *(const float2*)(bias + col);
            if (va) {
                float2 o;
                o.x = fmaxf(fmaf(acc[mi][t][0], inva, bb.x), 0.0f);
                o.y = fmaxf(fmaf(acc[mi][t][1], inva, bb.y), 0.0f);
                *(float2*)(out + (size_t)ra * CH + col) = o;
            }
            if (vb) {
                float2 o;
                o.x = fmaxf(fmaf(acc[mi][t][2], invb, bb.x), 0.0f);
                o.y = fmaxf(fmaf(acc[mi][t][3], invb, bb.y), 0.0f);
                *(float2*)(out + (size_t)rb2 * CH + col) = o;
            }
        }
    }
}

// ---------------------------------------------------------------------------
// kernel_launch
// Inputs: x[f32 N*128], edge_index[2*E], weight[f32 128*128],
//         u[f32 128], c[f32 1], bias[f32 128]
// u, c are dead: HEADS==1 => softmax over one element == 1.
// ---------------------------------------------------------------------------
extern "C" void kernel_launch(void* const* d_in, const int* in_sizes, int n_in,
                              void* d_out, int out_size) {
    const float* x    = (const float*)d_in[0];
    const void*  ei   = d_in[1];
    const float* W    = (const float*)d_in[2];
    const float* bias = (const float*)d_in[5];
    float* out = (float*)d_out;

    int n_nodes = in_sizes[0] / CH;
    int n_edges = in_sizes[1] / 2;

    static bool attr_set = false;
    if (!attr_set) {
        cudaFuncSetAttribute(gemm_mma_kernel,
                             cudaFuncAttributeMaxDynamicSharedMemorySize,
                             SM_TOTAL);
        attr_set = true;
    }

    zero_kernel<<<(n_nodes + 255) / 256, 256>>>(ei, n_nodes);
    wprep_kernel<<<(CH * LDA + 255) / 256, 256>>>(W);
    histo_fill_kernel<<<(n_edges + 255) / 256, 256>>>(ei, n_edges);
    gather_kernel<<<(n_nodes * 32 + 255) / 256, 256>>>(x, n_nodes);
    gemm_mma_kernel<<<(n_nodes + 127) / 128, 256, SM_TOTAL>>>(bias, out, n_nodes);
}

// round 7
// speedup vs baseline: 1.5488x; 1.0930x over previous
#include <cuda_runtime.h>
#include <cuda_bf16.h>
#include <cstdint>

// Problem constants (fixed shapes for this instance)
#define N_NODES 50000
#define N_EDGES 600000
#define CH      128          // IN_CH == OUT_CH == 128, HEADS == 1
#define CAP     96           // per-node bucket capacity
#define OVF_MAX 16384        // overflow edge list capacity (correctness fallback)

#define LDA 136              // padded bf16 row stride (272 B) for ldmatrix tiles

// ---------------------------------------------------------------------------
// Scratch (no cudaMalloc allowed)
// ---------------------------------------------------------------------------
__device__ __nv_bfloat16 d_shi[(size_t)N_NODES * CH];  // aggregated features, bf16 hi
__device__ __nv_bfloat16 d_slo[(size_t)N_NODES * CH];  // aggregated features, bf16 lo
__device__ int   d_deg[N_NODES];                   // in-degree (excl. self loop)
__device__ int   d_bucket[(size_t)N_NODES * CAP];  // per-dst source lists
__device__ int   d_is64;                           // edge_index dtype flag
__device__ int   d_ovf_cnt;
__device__ int   d_ovf[OVF_MAX * 2];
// W pre-transposed to [n][k] (k contiguous), bf16 hi/lo split, padded to LDA.
__device__ __nv_bfloat16 d_Whi[CH * LDA];
__device__ __nv_bfloat16 d_Wlo[CH * LDA];

// ---------------------------------------------------------------------------
// MMA helpers (baseline PTX, legal on plain sm_103)
// ---------------------------------------------------------------------------
__device__ __forceinline__ uint32_t smem_to_u32(const void* p) {
    uint32_t a;
    asm("{ .reg .u64 t; cvta.to.shared.u64 t, %1; cvt.u32.u64 %0, t; }"
        : "=r"(a) : "l"(p));
    return a;
}
__device__ __forceinline__ void ldsm_x4(uint32_t* r, uint32_t addr) {
    asm volatile("ldmatrix.sync.aligned.m8n8.x4.shared.b16 {%0,%1,%2,%3}, [%4];"
                 : "=r"(r[0]), "=r"(r[1]), "=r"(r[2]), "=r"(r[3]) : "r"(addr));
}
__device__ __forceinline__ void mma_bf16(float* c, const uint32_t* a,
                                         uint32_t b0, uint32_t b1) {
    asm volatile("mma.sync.aligned.m16n8k16.row.col.f32.bf16.bf16.f32 "
                 "{%0,%1,%2,%3}, {%4,%5,%6,%7}, {%8,%9}, {%0,%1,%2,%3};"
                 : "+f"(c[0]), "+f"(c[1]), "+f"(c[2]), "+f"(c[3])
                 : "r"(a[0]), "r"(a[1]), "r"(a[2]), "r"(a[3]), "r"(b0), "r"(b1));
}

// ---------------------------------------------------------------------------
// Prep: zero deg, transpose+split W, dtype sniff — one kernel, one launch.
// ---------------------------------------------------------------------------
__global__ void prep_kernel(const float* __restrict__ W,
                            const void* __restrict__ ei, int n_nodes) {
    int i = blockIdx.x * blockDim.x + threadIdx.x;
    if (i < n_nodes) d_deg[i] = 0;
    if (i < CH * LDA) {
        int n = i / LDA;
        int k = i % LDA;
        float w = (k < CH) ? W[(size_t)k * CH + n] : 0.0f;
        __nv_bfloat16 hi = __float2bfloat16(w);
        __nv_bfloat16 lo = __float2bfloat16(w - __bfloat162float(hi));
        d_Whi[i] = hi;
        d_Wlo[i] = lo;
    }
    if (i == 0) {
        d_ovf_cnt = 0;
        const unsigned long long* p = (const unsigned long long*)ei;
        int is64 = 1;
        #pragma unroll
        for (int j = 0; j < 16; j++)
            if (p[j] >> 32) is64 = 0;
        d_is64 = is64;
    }
}

// ---------------------------------------------------------------------------
// Histogram + bucket fill
// ---------------------------------------------------------------------------
__global__ void histo_fill_kernel(const void* __restrict__ ei, int n_edges) {
    int e = blockIdx.x * blockDim.x + threadIdx.x;
    if (e >= n_edges) return;
    int src, dst;
    if (d_is64) {
        const long long* p = (const long long*)ei;
        src = (int)p[e];
        dst = (int)p[n_edges + e];
    } else {
        const int* p = (const int*)ei;
        src = p[e];
        dst = p[n_edges + e];
    }
    int pos = atomicAdd(&d_deg[dst], 1);
    if (pos < CAP) {
        d_bucket[dst * CAP + pos] = src;
    } else {
        int j = atomicAdd(&d_ovf_cnt, 1);
        if (j < OVF_MAX) { d_ovf[2 * j] = src; d_ovf[2 * j + 1] = dst; }
    }
}

// ---------------------------------------------------------------------------
// Gather: warp per node; epilogue converts acc to bf16 hi/lo.
// 128-thread blocks (finer retirement granularity), L2-only neighbor loads.
// ---------------------------------------------------------------------------
__device__ __forceinline__ float4 ldcg4(const float* p) {
    float4 v;
    asm volatile("ld.global.cg.v4.f32 {%0,%1,%2,%3}, [%4];"
                 : "=f"(v.x), "=f"(v.y), "=f"(v.z), "=f"(v.w) : "l"(p));
    return v;
}

__global__ __launch_bounds__(128)
void gather_kernel(const float* __restrict__ x, int n_nodes) {
    int node = (blockIdx.x * blockDim.x + threadIdx.x) >> 5;
    int lane = threadIdx.x & 31;
    if (node >= n_nodes) return;

    int deg = d_deg[node];
    int nb  = min(deg, CAP);
    const size_t rb = (size_t)node * CH + lane * 4;
    float4 acc = *(const float4*)(x + rb);          // self loop

    int base = node * CAP;
    for (int e0 = 0; e0 < nb; e0 += 32) {
        int idx = 0;
        if (e0 + lane < nb) idx = d_bucket[base + e0 + lane];
        int m = min(32, nb - e0);
        int t = 0;
        for (; t + 4 <= m; t += 4) {
            int s0 = __shfl_sync(0xFFFFFFFFu, idx, t);
            int s1 = __shfl_sync(0xFFFFFFFFu, idx, t + 1);
            int s2 = __shfl_sync(0xFFFFFFFFu, idx, t + 2);
            int s3 = __shfl_sync(0xFFFFFFFFu, idx, t + 3);
            float4 v0 = ldcg4(x + (size_t)s0 * CH + lane * 4);
            float4 v1 = ldcg4(x + (size_t)s1 * CH + lane * 4);
            float4 v2 = ldcg4(x + (size_t)s2 * CH + lane * 4);
            float4 v3 = ldcg4(x + (size_t)s3 * CH + lane * 4);
            acc.x += v0.x + v1.x + v2.x + v3.x;
            acc.y += v0.y + v1.y + v2.y + v3.y;
            acc.z += v0.z + v1.z + v2.z + v3.z;
            acc.w += v0.w + v1.w + v2.w + v3.w;
        }
        for (; t < m; t++) {
            int s = __shfl_sync(0xFFFFFFFFu, idx, t);
            float4 v = ldcg4(x + (size_t)s * CH + lane * 4);
            acc.x += v.x; acc.y += v.y; acc.z += v.z; acc.w += v.w;
        }
    }
    if (deg > CAP) {   // never taken on this input
        int oc = min(d_ovf_cnt, OVF_MAX);
        for (int o = 0; o < oc; o++) {
            if (d_ovf[2 * o + 1] == node) {
                int s = d_ovf[2 * o];
                float4 v = ldcg4(x + (size_t)s * CH + lane * 4);
                acc.x += v.x; acc.y += v.y; acc.z += v.z; acc.w += v.w;
            }
        }
    }

    // bf16 hi/lo split (free here: kernel is memory-bound)
    float f[4] = {acc.x, acc.y, acc.z, acc.w};
    union { __nv_bfloat16 b[4]; uint2 v; } hi, lo;
    #pragma unroll
    for (int i = 0; i < 4; i++) {
        hi.b[i] = __float2bfloat16(f[i]);
        lo.b[i] = __float2bfloat16(f[i] - __bfloat162float(hi.b[i]));
    }
    *(uint2*)(d_shi + rb) = hi.v;
    *(uint2*)(d_slo + rb) = lo.v;
}

// ---------------------------------------------------------------------------
// Warp-MMA GEMM (bf16 HMMA, 3-term split): out = relu((s@W)/(deg+1) + bias)
// CTA: 128 rows x 128 cols x K=128. 8 warps, warp tile 32x64.
// A phase is now a pure linear copy (split was done in gather).
// ---------------------------------------------------------------------------
#define SA_HI 0
#define SA_LO (128 * LDA * 2)            // 34816
#define SB_HI (2 * 128 * LDA * 2)        // 69632
#define SB_LO (3 * 128 * LDA * 2)        // 104448
#define SM_TOTAL (4 * 128 * LDA * 2)     // 139264

__global__ __launch_bounds__(256, 1)
void gemm_mma_kernel(const float* __restrict__ bias,
                     float* __restrict__ out,
                     int n_nodes) {
    extern __shared__ char smem[];
    uint32_t sb = smem_to_u32(smem);
    int tid  = threadIdx.x;
    int wid  = tid >> 5;
    int lane = tid & 31;
    int row0 = blockIdx.x * 128;

    // ---- Copy A tile rows (bf16 hi/lo), 2 threads per row, 128B each ----
    {
        int row  = tid >> 1;
        int half = (tid & 1) * 64;            // bf16 elements
        int rg   = row0 + row;
        size_t goff = (size_t)rg * CH + half; // bf16 index
        size_t soff = ((size_t)row * LDA + half) * 2;
        if (rg < n_nodes) {
            const uint4* phi = (const uint4*)(d_shi + goff);
            const uint4* plo = (const uint4*)(d_slo + goff);
            #pragma unroll
            for (int j = 0; j < 8; j++) {
                *(uint4*)(smem + SA_HI + soff + j * 16) = phi[j];
                *(uint4*)(smem + SA_LO + soff + j * 16) = plo[j];
            }
        } else {
            uint4 z = make_uint4(0, 0, 0, 0);
            #pragma unroll
            for (int j = 0; j < 8; j++) {
                *(uint4*)(smem + SA_HI + soff + j * 16) = z;
                *(uint4*)(smem + SA_LO + soff + j * 16) = z;
            }
        }
    }
    // ---- Copy pre-split B tiles (linear, 2176 uint4 each) ----
    {
        const uint4* shi = (const uint4*)d_Whi;
        const uint4* slo = (const uint4*)d_Wlo;
        uint4* dhi = (uint4*)(smem + SB_HI);
        uint4* dlo = (uint4*)(smem + SB_LO);
        #pragma unroll
        for (int i = 0; i < 9; i++) {
            int idx = tid + i * 256;
            if (idx < (128 * LDA * 2) / 16) {
                dhi[idx] = shi[idx];
                dlo[idx] = slo[idx];
            }
        }
    }
    __syncthreads();

    // ---- Warp MMA mainloop ----
    int mw = (wid >> 1) * 32;      // warp M offset
    int nw = (wid & 1) * 64;       // warp N offset
    int lr = lane & 15;
    int lh = lane >> 4;

    float acc[2][8][4];
    #pragma unroll
    for (int mi = 0; mi < 2; mi++)
        #pragma unroll
        for (int t = 0; t < 8; t++)
            #pragma unroll
            for (int j = 0; j < 4; j++) acc[mi][t][j] = 0.0f;

    #pragma unroll
    for (int kk = 0; kk < 8; kk++) {
        int k0 = kk * 16;
        uint32_t ahi[2][4], alo[2][4], bhi[4][4], blo[4][4];
        #pragma unroll
        for (int mi = 0; mi < 2; mi++) {
            uint32_t ar = sb + SA_HI + ((mw + mi * 16 + lr) * LDA + k0 + lh * 8) * 2;
            ldsm_x4(ahi[mi], ar);
            ldsm_x4(alo[mi], ar + (SA_LO - SA_HI));
        }
        #pragma unroll
        for (int nj = 0; nj < 4; nj++) {
            uint32_t br = sb + SB_HI + ((nw + nj * 16 + lr) * LDA + k0 + lh * 8) * 2;
            ldsm_x4(bhi[nj], br);
            ldsm_x4(blo[nj], br + (SB_LO - SB_HI));
        }
        #pragma unroll
        for (int mi = 0; mi < 2; mi++) {
            #pragma unroll
            for (int t = 0; t < 8; t++) {
                int nj  = t >> 1;
                int sel = t & 1;
                uint32_t bh0 = bhi[nj][sel],     bh1 = bhi[nj][sel + 2];
                uint32_t bl0 = blo[nj][sel],     bl1 = blo[nj][sel + 2];
                mma_bf16(acc[mi][t], ahi[mi], bh0, bh1);   // hi*hi
                mma_bf16(acc[mi][t], ahi[mi], bl0, bl1);   // hi*lo
                mma_bf16(acc[mi][t], alo[mi], bh0, bh1);   // lo*hi
            }
        }
    }

    // ---- Epilogue: /(deg+1), +bias, relu ----
    int qr = lane >> 2;
    int qc = lane & 3;
    #pragma unroll
    for (int mi = 0; mi < 2; mi++) {
        int ra = row0 + mw + mi * 16 + qr;
        int rb2 = ra + 8;
        bool va = ra < n_nodes, vb = rb2 < n_nodes;
        float inva = va ? 1.0f / (float)(d_deg[ra] + 1) : 0.0f;
        float invb = vb ? 1.0f / (float)(d_deg[rb2] + 1) : 0.0f;
        #pragma unroll
        for (int t = 0; t < 8; t++) {
            int col = nw + t * 8 + qc * 2;
            float2 bb = *(const float2*)(bias + col);
            if (va) {
                float2 o;
                o.x = fmaxf(fmaf(acc[mi][t][0], inva, bb.x), 0.0f);
                o.y = fmaxf(fmaf(acc[mi][t][1], inva, bb.y), 0.0f);
                *(float2*)(out + (size_t)ra * CH + col) = o;
            }
            if (vb) {
                float2 o;
                o.x = fmaxf(fmaf(acc[mi][t][2], invb, bb.x), 0.0f);
                o.y = fmaxf(fmaf(acc[mi][t][3], invb, bb.y), 0.0f);
                *(float2*)(out + (size_t)rb2 * CH + col) = o;
            }
        }
    }
}

// ---------------------------------------------------------------------------
// kernel_launch
// Inputs: x[f32 N*128], edge_index[2*E], weight[f32 128*128],
//         u[f32 128], c[f32 1], bias[f32 128]
// u, c are dead: HEADS==1 => softmax over one element == 1.
// ---------------------------------------------------------------------------
extern "C" void kernel_launch(void* const* d_in, const int* in_sizes, int n_in,
                              void* d_out, int out_size) {
    const float* x    = (const float*)d_in[0];
    const void*  ei   = d_in[1];
    const float* W    = (const float*)d_in[2];
    const float* bias = (const float*)d_in[5];
    float* out = (float*)d_out;

    int n_nodes = in_sizes[0] / CH;
    int n_edges = in_sizes[1] / 2;

    static bool attr_set = false;
    if (!attr_set) {
        cudaFuncSetAttribute(gemm_mma_kernel,
                             cudaFuncAttributeMaxDynamicSharedMemorySize,
                             SM_TOTAL);
        attr_set = true;
    }

    int prep_threads = (n_nodes > CH * LDA) ? n_nodes : CH * LDA;
    prep_kernel<<<(prep_threads + 255) / 256, 256>>>(W, ei, n_nodes);
    histo_fill_kernel<<<(n_edges + 255) / 256, 256>>>(ei, n_edges);
    gather_kernel<<<(n_nodes * 32 + 127) / 128, 128>>>(x, n_nodes);
    gemm_mma_kernel<<<(n_nodes + 127) / 128, 256, SM_TOTAL>>>(bias, out, n_nodes);
}

// round 8
// speedup vs baseline: 1.6332x; 1.0545x over previous
#include <cuda_runtime.h>
#include <cuda_bf16.h>
#include <cstdint>

// Problem constants (fixed shapes for this instance)
#define N_NODES 50000
#define N_EDGES 600000
#define CH      128          // IN_CH == OUT_CH == 128, HEADS == 1
#define CAP     96           // per-node bucket capacity
#define OVF_MAX 16384        // overflow edge list capacity (correctness fallback)

#define LDA 136              // padded bf16 row stride (272 B) for ldmatrix tiles

// ---------------------------------------------------------------------------
// Scratch (no cudaMalloc allowed)
// ---------------------------------------------------------------------------
__device__ __nv_bfloat16 d_shi[(size_t)N_NODES * CH];  // aggregated features, bf16 hi
__device__ __nv_bfloat16 d_slo[(size_t)N_NODES * CH];  // aggregated features, bf16 lo
__device__ int   d_deg[N_NODES];                   // in-degree (excl. self loop)
__device__ int   d_bucket[(size_t)N_NODES * CAP];  // per-dst source lists
__device__ int   d_is64;                           // edge_index dtype flag
__device__ int   d_ovf_cnt;
__device__ int   d_ovf[OVF_MAX * 2];
// W pre-transposed to [n][k] (k contiguous), bf16 hi/lo split, padded to LDA.
__device__ __nv_bfloat16 d_Whi[CH * LDA];
__device__ __nv_bfloat16 d_Wlo[CH * LDA];

// ---------------------------------------------------------------------------
// MMA helpers (baseline PTX, legal on plain sm_103)
// ---------------------------------------------------------------------------
__device__ __forceinline__ uint32_t smem_to_u32(const void* p) {
    uint32_t a;
    asm("{ .reg .u64 t; cvta.to.shared.u64 t, %1; cvt.u32.u64 %0, t; }"
        : "=r"(a) : "l"(p));
    return a;
}
__device__ __forceinline__ void ldsm_x4(uint32_t* r, uint32_t addr) {
    asm volatile("ldmatrix.sync.aligned.m8n8.x4.shared.b16 {%0,%1,%2,%3}, [%4];"
                 : "=r"(r[0]), "=r"(r[1]), "=r"(r[2]), "=r"(r[3]) : "r"(addr));
}
__device__ __forceinline__ void mma_bf16(float* c, const uint32_t* a,
                                         uint32_t b0, uint32_t b1) {
    asm volatile("mma.sync.aligned.m16n8k16.row.col.f32.bf16.bf16.f32 "
                 "{%0,%1,%2,%3}, {%4,%5,%6,%7}, {%8,%9}, {%0,%1,%2,%3};"
                 : "+f"(c[0]), "+f"(c[1]), "+f"(c[2]), "+f"(c[3])
                 : "r"(a[0]), "r"(a[1]), "r"(a[2]), "r"(a[3]), "r"(b0), "r"(b1));
}

// ---------------------------------------------------------------------------
// Prep: zero deg, transpose+split W, dtype sniff — one kernel, one launch.
// ---------------------------------------------------------------------------
__global__ void prep_kernel(const float* __restrict__ W,
                            const void* __restrict__ ei, int n_nodes) {
    int i = blockIdx.x * blockDim.x + threadIdx.x;
    if (i < n_nodes) d_deg[i] = 0;
    if (i < CH * LDA) {
        int n = i / LDA;
        int k = i % LDA;
        float w = (k < CH) ? W[(size_t)k * CH + n] : 0.0f;
        __nv_bfloat16 hi = __float2bfloat16(w);
        __nv_bfloat16 lo = __float2bfloat16(w - __bfloat162float(hi));
        d_Whi[i] = hi;
        d_Wlo[i] = lo;
    }
    if (i == 0) {
        d_ovf_cnt = 0;
        const unsigned long long* p = (const unsigned long long*)ei;
        int is64 = 1;
        #pragma unroll
        for (int j = 0; j < 16; j++)
            if (p[j] >> 32) is64 = 0;
        d_is64 = is64;
    }
}

// ---------------------------------------------------------------------------
// Histogram + bucket fill
// ---------------------------------------------------------------------------
__global__ void histo_fill_kernel(const void* __restrict__ ei, int n_edges) {
    int e = blockIdx.x * blockDim.x + threadIdx.x;
    if (e >= n_edges) return;
    int src, dst;
    if (d_is64) {
        const long long* p = (const long long*)ei;
        src = (int)p[e];
        dst = (int)p[n_edges + e];
    } else {
        const int* p = (const int*)ei;
        src = p[e];
        dst = p[n_edges + e];
    }
    int pos = atomicAdd(&d_deg[dst], 1);
    if (pos < CAP) {
        d_bucket[dst * CAP + pos] = src;
    } else {
        int j = atomicAdd(&d_ovf_cnt, 1);
        if (j < OVF_MAX) { d_ovf[2 * j] = src; d_ovf[2 * j + 1] = dst; }
    }
}

// ---------------------------------------------------------------------------
// Gather: warp per node; epilogue converts acc to bf16 hi/lo.
// ---------------------------------------------------------------------------
__device__ __forceinline__ float4 ldcg4(const float* p) {
    float4 v;
    asm volatile("ld.global.cg.v4.f32 {%0,%1,%2,%3}, [%4];"
                 : "=f"(v.x), "=f"(v.y), "=f"(v.z), "=f"(v.w) : "l"(p));
    return v;
}

__global__ __launch_bounds__(128)
void gather_kernel(const float* __restrict__ x, int n_nodes) {
    int node = (blockIdx.x * blockDim.x + threadIdx.x) >> 5;
    int lane = threadIdx.x & 31;
    if (node >= n_nodes) return;

    int deg = d_deg[node];
    int nb  = min(deg, CAP);
    const size_t rb = (size_t)node * CH + lane * 4;
    float4 acc = *(const float4*)(x + rb);          // self loop

    int base = node * CAP;
    for (int e0 = 0; e0 < nb; e0 += 32) {
        int idx = 0;
        if (e0 + lane < nb) idx = d_bucket[base + e0 + lane];
        int m = min(32, nb - e0);
        int t = 0;
        for (; t + 4 <= m; t += 4) {
            int s0 = __shfl_sync(0xFFFFFFFFu, idx, t);
            int s1 = __shfl_sync(0xFFFFFFFFu, idx, t + 1);
            int s2 = __shfl_sync(0xFFFFFFFFu, idx, t + 2);
            int s3 = __shfl_sync(0xFFFFFFFFu, idx, t + 3);
            float4 v0 = ldcg4(x + (size_t)s0 * CH + lane * 4);
            float4 v1 = ldcg4(x + (size_t)s1 * CH + lane * 4);
            float4 v2 = ldcg4(x + (size_t)s2 * CH + lane * 4);
            float4 v3 = ldcg4(x + (size_t)s3 * CH + lane * 4);
            acc.x += v0.x + v1.x + v2.x + v3.x;
            acc.y += v0.y + v1.y + v2.y + v3.y;
            acc.z += v0.z + v1.z + v2.z + v3.z;
            acc.w += v0.w + v1.w + v2.w + v3.w;
        }
        for (; t < m; t++) {
            int s = __shfl_sync(0xFFFFFFFFu, idx, t);
            float4 v = ldcg4(x + (size_t)s * CH + lane * 4);
            acc.x += v.x; acc.y += v.y; acc.z += v.z; acc.w += v.w;
        }
    }
    if (deg > CAP) {   // never taken on this input
        int oc = min(d_ovf_cnt, OVF_MAX);
        for (int o = 0; o < oc; o++) {
            if (d_ovf[2 * o + 1] == node) {
                int s = d_ovf[2 * o];
                float4 v = ldcg4(x + (size_t)s * CH + lane * 4);
                acc.x += v.x; acc.y += v.y; acc.z += v.z; acc.w += v.w;
            }
        }
    }

    float f[4] = {acc.x, acc.y, acc.z, acc.w};
    union { __nv_bfloat16 b[4]; uint2 v; } hi, lo;
    #pragma unroll
    for (int i = 0; i < 4; i++) {
        hi.b[i] = __float2bfloat16(f[i]);
        lo.b[i] = __float2bfloat16(f[i] - __bfloat162float(hi.b[i]));
    }
    *(uint2*)(d_shi + rb) = hi.v;
    *(uint2*)(d_slo + rb) = lo.v;
}

// ---------------------------------------------------------------------------
// Warp-MMA GEMM (bf16 HMMA, 3-term split): out = relu((s@W)/(deg+1) + bias)
// CTA: M=64 x N=128 x K=128; 8 warps, warp tile 16x64. 2 CTAs/SM.
// Mainloop ordered by pass so same-acc MMAs are 8 apart (ILP).
// ---------------------------------------------------------------------------
#define SA_HI 0
#define SA_LO (64 * LDA * 2)             // 17408
#define SB_HI (2 * 64 * LDA * 2)         // 34816
#define SB_LO (SB_HI + 128 * LDA * 2)    // 69632
#define SM_TOTAL (SB_HI + 2 * 128 * LDA * 2)   // 104448

__global__ __launch_bounds__(256, 2)
void gemm_mma_kernel(const float* __restrict__ bias,
                     float* __restrict__ out,
                     int n_nodes) {
    extern __shared__ char smem[];
    uint32_t sb = smem_to_u32(smem);
    int tid  = threadIdx.x;
    int wid  = tid >> 5;
    int lane = tid & 31;
    int row0 = blockIdx.x * 64;

    // ---- Copy A tile rows (bf16 hi/lo): 4 threads per row, 64B each ----
    {
        int row = tid >> 2;              // 0..63
        int q   = tid & 3;               // quarter: 32 bf16 = 64 B
        int rg  = row0 + row;
        size_t goff = (size_t)rg * CH + q * 32;
        size_t soff = ((size_t)row * LDA + q * 32) * 2;
        if (rg < n_nodes) {
            const uint4* phi = (const uint4*)(d_shi + goff);
            const uint4* plo = (const uint4*)(d_slo + goff);
            #pragma unroll
            for (int j = 0; j < 4; j++) {
                *(uint4*)(smem + SA_HI + soff + j * 16) = phi[j];
                *(uint4*)(smem + SA_LO + soff + j * 16) = plo[j];
            }
        } else {
            uint4 z = make_uint4(0, 0, 0, 0);
            #pragma unroll
            for (int j = 0; j < 4; j++) {
                *(uint4*)(smem + SA_HI + soff + j * 16) = z;
                *(uint4*)(smem + SA_LO + soff + j * 16) = z;
            }
        }
    }
    // ---- Copy pre-split B tiles (linear, 2176 uint4 each) ----
    {
        const uint4* shi = (const uint4*)d_Whi;
        const uint4* slo = (const uint4*)d_Wlo;
        uint4* dhi = (uint4*)(smem + SB_HI);
        uint4* dlo = (uint4*)(smem + SB_LO);
        #pragma unroll
        for (int i = 0; i < 9; i++) {
            int idx = tid + i * 256;
            if (idx < (128 * LDA * 2) / 16) {
                dhi[idx] = shi[idx];
                dlo[idx] = slo[idx];
            }
        }
    }
    __syncthreads();

    // ---- Warp MMA mainloop: warp tile 16 rows x 64 cols ----
    int mw = (wid & 3) * 16;       // warp M offset (0..48)
    int nw = (wid >> 2) * 64;      // warp N offset (0 or 64)
    int lr = lane & 15;
    int lh = lane >> 4;

    float acc[8][4];
    #pragma unroll
    for (int t = 0; t < 8; t++)
        #pragma unroll
        for (int j = 0; j < 4; j++) acc[t][j] = 0.0f;

    #pragma unroll
    for (int kk = 0; kk < 8; kk++) {
        int k0 = kk * 16;
        uint32_t ahi[4], alo[4], bhi[4][4], blo[4][4];
        {
            uint32_t ar = sb + SA_HI + ((mw + lr) * LDA + k0 + lh * 8) * 2;
            ldsm_x4(ahi, ar);
            ldsm_x4(alo, ar + (SA_LO - SA_HI));
        }
        #pragma unroll
        for (int nj = 0; nj < 4; nj++) {
            uint32_t br = sb + SB_HI + ((nw + nj * 16 + lr) * LDA + k0 + lh * 8) * 2;
            ldsm_x4(bhi[nj], br);
            ldsm_x4(blo[nj], br + (SB_LO - SB_HI));
        }
        // Pass-ordered: same-acc MMAs are 8 independent instrs apart.
        #pragma unroll
        for (int t = 0; t < 8; t++)
            mma_bf16(acc[t], ahi, bhi[t >> 1][t & 1], bhi[t >> 1][(t & 1) + 2]);
        #pragma unroll
        for (int t = 0; t < 8; t++)
            mma_bf16(acc[t], ahi, blo[t >> 1][t & 1], blo[t >> 1][(t & 1) + 2]);
        #pragma unroll
        for (int t = 0; t < 8; t++)
            mma_bf16(acc[t], alo, bhi[t >> 1][t & 1], bhi[t >> 1][(t & 1) + 2]);
    }

    // ---- Epilogue: /(deg+1), +bias, relu ----
    int qr = lane >> 2;
    int qc = lane & 3;
    int ra  = row0 + mw + qr;
    int rb2 = ra + 8;
    bool va = ra < n_nodes, vb = rb2 < n_nodes;
    float inva = va ? 1.0f / (float)(d_deg[ra] + 1) : 0.0f;
    float invb = vb ? 1.0f / (float)(d_deg[rb2] + 1) : 0.0f;
    #pragma unroll
    for (int t = 0; t < 8; t++) {
        int col = nw + t * 8 + qc * 2;
        float2 bb = *(const float2*)(bias + col);
        if (va) {
            float2 o;
            o.x = fmaxf(fmaf(acc[t][0], inva, bb.x), 0.0f);
            o.y = fmaxf(fmaf(acc[t][1], inva, bb.y), 0.0f);
            *(float2*)(out + (size_t)ra * CH + col) = o;
        }
        if (vb) {
            float2 o;
            o.x = fmaxf(fmaf(acc[t][2], invb, bb.x), 0.0f);
            o.y = fmaxf(fmaf(acc[t][3], invb, bb.y), 0.0f);
            *(float2*)(out + (size_t)rb2 * CH + col) = o;
        }
    }
}

// ---------------------------------------------------------------------------
// kernel_launch
// Inputs: x[f32 N*128], edge_index[2*E], weight[f32 128*128],
//         u[f32 128], c[f32 1], bias[f32 128]
// u, c are dead: HEADS==1 => softmax over one element == 1.
// ---------------------------------------------------------------------------
extern "C" void kernel_launch(void* const* d_in, const int* in_sizes, int n_in,
                              void* d_out, int out_size) {
    const float* x    = (const float*)d_in[0];
    const void*  ei   = d_in[1];
    const float* W    = (const float*)d_in[2];
    const float* bias = (const float*)d_in[5];
    float* out = (float*)d_out;

    int n_nodes = in_sizes[0] / CH;
    int n_edges = in_sizes[1] / 2;

    static bool attr_set = false;
    if (!attr_set) {
        cudaFuncSetAttribute(gemm_mma_kernel,
                             cudaFuncAttributeMaxDynamicSharedMemorySize,
                             SM_TOTAL);
        attr_set = true;
    }

    int prep_threads = (n_nodes > CH * LDA) ? n_nodes : CH * LDA;
    prep_kernel<<<(prep_threads + 255) / 256, 256>>>(W, ei, n_nodes);
    histo_fill_kernel<<<(n_edges + 255) / 256, 256>>>(ei, n_edges);
    gather_kernel<<<(n_nodes * 32 + 127) / 128, 128>>>(x, n_nodes);
    gemm_mma_kernel<<<(n_nodes + 63) / 64, 256, SM_TOTAL>>>(bias, out, n_nodes);
}

// round 9
// speedup vs baseline: 2.0327x; 1.2446x over previous
#include <cuda_runtime.h>
#include <cuda_fp16.h>
#include <cstdint>

// Problem constants (fixed shapes for this instance)
#define N_NODES 50000
#define N_EDGES 600000
#define CH      128          // IN_CH == OUT_CH == 128, HEADS == 1
#define CAP     96           // per-node bucket capacity
#define OVF_MAX 16384        // overflow edge list capacity (correctness fallback)

#define LDA 136              // padded fp16 row stride (272 B) for ldmatrix tiles

// ---------------------------------------------------------------------------
// Scratch (no cudaMalloc allowed)
// ---------------------------------------------------------------------------
__device__ __half d_xh[(size_t)N_NODES * CH];      // x in fp16
__device__ __half d_sh[(size_t)N_NODES * CH];      // aggregated features, fp16
__device__ int    d_deg[N_NODES];                  // in-degree (excl. self loop)
__device__ int    d_bucket[(size_t)N_NODES * CAP]; // per-dst source lists
__device__ int    d_is64;                          // edge_index dtype flag
__device__ int    d_ovf_cnt;
__device__ int    d_ovf[OVF_MAX * 2];
__device__ __half d_Wh[CH * LDA];                  // W^T [n][k], fp16, padded

// ---------------------------------------------------------------------------
// MMA helpers (baseline PTX, legal on plain sm_103)
// ---------------------------------------------------------------------------
__device__ __forceinline__ uint32_t smem_to_u32(const void* p) {
    uint32_t a;
    asm("{ .reg .u64 t; cvta.to.shared.u64 t, %1; cvt.u32.u64 %0, t; }"
        : "=r"(a) : "l"(p));
    return a;
}
__device__ __forceinline__ void ldsm_x4(uint32_t* r, uint32_t addr) {
    asm volatile("ldmatrix.sync.aligned.m8n8.x4.shared.b16 {%0,%1,%2,%3}, [%4];"
                 : "=r"(r[0]), "=r"(r[1]), "=r"(r[2]), "=r"(r[3]) : "r"(addr));
}
__device__ __forceinline__ void mma_fp16(float* c, const uint32_t* a,
                                         uint32_t b0, uint32_t b1) {
    asm volatile("mma.sync.aligned.m16n8k16.row.col.f32.f16.f16.f32 "
                 "{%0,%1,%2,%3}, {%4,%5,%6,%7}, {%8,%9}, {%0,%1,%2,%3};"
                 : "+f"(c[0]), "+f"(c[1]), "+f"(c[2]), "+f"(c[3])
                 : "r"(a[0]), "r"(a[1]), "r"(a[2]), "r"(a[3]), "r"(b0), "r"(b1));
}

// ---------------------------------------------------------------------------
// Prep: x -> fp16, W -> fp16 [n][k] padded, zero deg, sniff dtype. One launch.
// ---------------------------------------------------------------------------
__global__ void prep_kernel(const float* __restrict__ x,
                            const float* __restrict__ W,
                            const void* __restrict__ ei, int n_nodes) {
    int i = blockIdx.x * blockDim.x + threadIdx.x;
    int n4 = n_nodes * (CH / 4);
    if (i < n4) {
        float4 v = *(const float4*)(x + (size_t)i * 4);
        __half2 h01 = __floats2half2_rn(v.x, v.y);
        __half2 h23 = __floats2half2_rn(v.z, v.w);
        uint2 pack;
        pack.x = *(uint32_t*)&h01;
        pack.y = *(uint32_t*)&h23;
        *(uint2*)(d_xh + (size_t)i * 4) = pack;
    }
    if (i < n_nodes) d_deg[i] = 0;
    if (i < CH * LDA) {
        int n = i / LDA;
        int k = i % LDA;
        float w = (k < CH) ? W[(size_t)k * CH + n] : 0.0f;
        d_Wh[i] = __float2half_rn(w);
    }
    if (i == 0) {
        d_ovf_cnt = 0;
        const unsigned long long* p = (const unsigned long long*)ei;
        int is64 = 1;
        #pragma unroll
        for (int j = 0; j < 16; j++)
            if (p[j] >> 32) is64 = 0;
        d_is64 = is64;
    }
}

// ---------------------------------------------------------------------------
// Histogram + bucket fill
// ---------------------------------------------------------------------------
__global__ void histo_fill_kernel(const void* __restrict__ ei, int n_edges) {
    int e = blockIdx.x * blockDim.x + threadIdx.x;
    if (e >= n_edges) return;
    int src, dst;
    if (d_is64) {
        const long long* p = (const long long*)ei;
        src = (int)p[e];
        dst = (int)p[n_edges + e];
    } else {
        const int* p = (const int*)ei;
        src = p[e];
        dst = p[n_edges + e];
    }
    int pos = atomicAdd(&d_deg[dst], 1);
    if (pos < CAP) {
        d_bucket[dst * CAP + pos] = src;
    } else {
        int j = atomicAdd(&d_ovf_cnt, 1);
        if (j < OVF_MAX) { d_ovf[2 * j] = src; d_ovf[2 * j + 1] = dst; }
    }
}

// ---------------------------------------------------------------------------
// Gather: warp per node, fp16 neighbor rows (256 B/edge), fp32 accumulate.
// Each lane owns 4 channels (one uint2 = 4 halfs). Output s in fp16.
// ---------------------------------------------------------------------------
__device__ __forceinline__ uint2 ldcg2(const __half* p) {
    uint2 v;
    asm volatile("ld.global.cg.v2.u32 {%0,%1}, [%2];"
                 : "=r"(v.x), "=r"(v.y) : "l"(p));
    return v;
}
__device__ __forceinline__ void acc_h4(float* f, uint2 v) {
    __half2 h01 = *(__half2*)&v.x;
    __half2 h23 = *(__half2*)&v.y;
    float2 f01 = __half22float2(h01);
    float2 f23 = __half22float2(h23);
    f[0] += f01.x; f[1] += f01.y; f[2] += f23.x; f[3] += f23.y;
}

__global__ __launch_bounds__(128)
void gather_kernel(int n_nodes) {
    int node = (blockIdx.x * blockDim.x + threadIdx.x) >> 5;
    int lane = threadIdx.x & 31;
    if (node >= n_nodes) return;

    int deg = d_deg[node];
    int nb  = min(deg, CAP);
    const size_t rb = (size_t)node * CH + lane * 4;

    float acc[4] = {0.f, 0.f, 0.f, 0.f};
    acc_h4(acc, ldcg2(d_xh + rb));                 // self loop

    int base = node * CAP;
    for (int e0 = 0; e0 < nb; e0 += 32) {
        int idx = 0;
        if (e0 + lane < nb) idx = d_bucket[base + e0 + lane];
        int m = min(32, nb - e0);
        int t = 0;
        for (; t + 4 <= m; t += 4) {
            int s0 = __shfl_sync(0xFFFFFFFFu, idx, t);
            int s1 = __shfl_sync(0xFFFFFFFFu, idx, t + 1);
            int s2 = __shfl_sync(0xFFFFFFFFu, idx, t + 2);
            int s3 = __shfl_sync(0xFFFFFFFFu, idx, t + 3);
            uint2 v0 = ldcg2(d_xh + (size_t)s0 * CH + lane * 4);
            uint2 v1 = ldcg2(d_xh + (size_t)s1 * CH + lane * 4);
            uint2 v2 = ldcg2(d_xh + (size_t)s2 * CH + lane * 4);
            uint2 v3 = ldcg2(d_xh + (size_t)s3 * CH + lane * 4);
            acc_h4(acc, v0); acc_h4(acc, v1); acc_h4(acc, v2); acc_h4(acc, v3);
        }
        for (; t < m; t++) {
            int s = __shfl_sync(0xFFFFFFFFu, idx, t);
            acc_h4(acc, ldcg2(d_xh + (size_t)s * CH + lane * 4));
        }
    }
    if (deg > CAP) {   // never taken on this input
        int oc = min(d_ovf_cnt, OVF_MAX);
        for (int o = 0; o < oc; o++) {
            if (d_ovf[2 * o + 1] == node) {
                int s = d_ovf[2 * o];
                acc_h4(acc, ldcg2(d_xh + (size_t)s * CH + lane * 4));
            }
        }
    }

    __half2 h01 = __floats2half2_rn(acc[0], acc[1]);
    __half2 h23 = __floats2half2_rn(acc[2], acc[3]);
    uint2 pack;
    pack.x = *(uint32_t*)&h01;
    pack.y = *(uint32_t*)&h23;
    *(uint2*)(d_sh + rb) = pack;
}

// ---------------------------------------------------------------------------
// Warp-MMA GEMM (plain fp16 HMMA): out = relu((s@W)/(deg+1) + bias)
// CTA: M=64 x N=128 x K=128; 8 warps, warp tile 16x64; 4 CTAs/SM.
// ---------------------------------------------------------------------------
#define SA 0
#define SB (64 * LDA * 2)                 // 17408
#define SM_TOTAL (SB + 128 * LDA * 2)     // 52224

__global__ __launch_bounds__(256, 4)
void gemm_mma_kernel(const float* __restrict__ bias,
                     float* __restrict__ out,
                     int n_nodes) {
    extern __shared__ char smem[];
    uint32_t sb = smem_to_u32(smem);
    int tid  = threadIdx.x;
    int wid  = tid >> 5;
    int lane = tid & 31;
    int row0 = blockIdx.x * 64;

    // ---- Copy A tile rows (fp16): 4 threads per row, 64 B each ----
    {
        int row = tid >> 2;              // 0..63
        int q   = tid & 3;               // quarter: 32 halfs = 64 B
        int rg  = row0 + row;
        size_t goff = (size_t)rg * CH + q * 32;
        size_t soff = ((size_t)row * LDA + q * 32) * 2;
        if (rg < n_nodes) {
            const uint4* ph = (const uint4*)(d_sh + goff);
            #pragma unroll
            for (int j = 0; j < 4; j++)
                *(uint4*)(smem + SA + soff + j * 16) = ph[j];
        } else {
            uint4 z = make_uint4(0, 0, 0, 0);
            #pragma unroll
            for (int j = 0; j < 4; j++)
                *(uint4*)(smem + SA + soff + j * 16) = z;
        }
    }
    // ---- Copy B tile (linear, 2176 uint4) ----
    {
        const uint4* sw = (const uint4*)d_Wh;
        uint4* dw = (uint4*)(smem + SB);
        #pragma unroll
        for (int i = 0; i < 9; i++) {
            int idx = tid + i * 256;
            if (idx < (128 * LDA * 2) / 16) dw[idx] = sw[idx];
        }
    }
    __syncthreads();

    // ---- Warp MMA mainloop: warp tile 16 rows x 64 cols ----
    int mw = (wid & 3) * 16;       // warp M offset (0..48)
    int nw = (wid >> 2) * 64;      // warp N offset (0 or 64)
    int lr = lane & 15;
    int lh = lane >> 4;

    float acc[8][4];
    #pragma unroll
    for (int t = 0; t < 8; t++)
        #pragma unroll
        for (int j = 0; j < 4; j++) acc[t][j] = 0.0f;

    #pragma unroll
    for (int kk = 0; kk < 8; kk++) {
        int k0 = kk * 16;
        uint32_t a[4], b[4][4];
        ldsm_x4(a, sb + SA + ((mw + lr) * LDA + k0 + lh * 8) * 2);
        #pragma unroll
        for (int nj = 0; nj < 4; nj++)
            ldsm_x4(b[nj], sb + SB + ((nw + nj * 16 + lr) * LDA + k0 + lh * 8) * 2);
        #pragma unroll
        for (int t = 0; t < 8; t++)
            mma_fp16(acc[t], a, b[t >> 1][t & 1], b[t >> 1][(t & 1) + 2]);
    }

    // ---- Epilogue: /(deg+1), +bias, relu ----
    int qr = lane >> 2;
    int qc = lane & 3;
    int ra  = row0 + mw + qr;
    int rb2 = ra + 8;
    bool va = ra < n_nodes, vb = rb2 < n_nodes;
    float inva = va ? 1.0f / (float)(d_deg[ra] + 1) : 0.0f;
    float invb = vb ? 1.0f / (float)(d_deg[rb2] + 1) : 0.0f;
    #pragma unroll
    for (int t = 0; t < 8; t++) {
        int col = nw + t * 8 + qc * 2;
        float2 bb = *(const float2*)(bias + col);
        if (va) {
            float2 o;
            o.x = fmaxf(fmaf(acc[t][0], inva, bb.x), 0.0f);
            o.y = fmaxf(fmaf(acc[t][1], inva, bb.y), 0.0f);
            *(float2*)(out + (size_t)ra * CH + col) = o;
        }
        if (vb) {
            float2 o;
            o.x = fmaxf(fmaf(acc[t][2], invb, bb.x), 0.0f);
            o.y = fmaxf(fmaf(acc[t][3], invb, bb.y), 0.0f);
            *(float2*)(out + (size_t)rb2 * CH + col) = o;
        }
    }
}

// ---------------------------------------------------------------------------
// kernel_launch
// Inputs: x[f32 N*128], edge_index[2*E], weight[f32 128*128],
//         u[f32 128], c[f32 1], bias[f32 128]
// u, c are dead: HEADS==1 => softmax over one element == 1.
// ---------------------------------------------------------------------------
extern "C" void kernel_launch(void* const* d_in, const int* in_sizes, int n_in,
                              void* d_out, int out_size) {
    const float* x    = (const float*)d_in[0];
    const void*  ei   = d_in[1];
    const float* W    = (const float*)d_in[2];
    const float* bias = (const float*)d_in[5];
    float* out = (float*)d_out;

    int n_nodes = in_sizes[0] / CH;
    int n_edges = in_sizes[1] / 2;

    static bool attr_set = false;
    if (!attr_set) {
        cudaFuncSetAttribute(gemm_mma_kernel,
                             cudaFuncAttributeMaxDynamicSharedMemorySize,
                             SM_TOTAL);
        attr_set = true;
    }

    int prep_threads = n_nodes * (CH / 4);        // 1.6M, covers all prep work
    prep_kernel<<<(prep_threads + 255) / 256, 256>>>(x, W, ei, n_nodes);
    histo_fill_kernel<<<(n_edges + 255) / 256, 256>>>(ei, n_edges);
    gather_kernel<<<(n_nodes * 32 + 127) / 128, 128>>>(n_nodes);
    gemm_mma_kernel<<<(n_nodes + 63) / 64, 256, SM_TOTAL>>>(bias, out, n_nodes);
}